// round 12
// baseline (speedup 1.0000x reference)
#include <cuda_runtime.h>
#include <cstdint>
#include <cstddef>

#define NT    4096      // H*W tokens
#define CH    256       // hidden channels
#define CIN   512       // input channels
#define BATCH 4

// ---------------- scratch (device globals; no allocation in kernel_launch) --------
__device__ float d_fT [(size_t)BATCH * NT * CH];   // fT [b][n][d]
__device__ float d_gT [(size_t)BATCH * NT * CH];   // gT [b][m][d]
__device__ float d_h  [(size_t)BATCH * CH * NT];   // h  [b][d][m]
__device__ float d_fcs[(size_t)BATCH * NT * CH];   // Fcs[b][n][d]
__device__ float d_S  [(size_t)BATCH * NT * NT];   // scores / probs [b][n][m]
__device__ float d_mean[2 * BATCH * CIN];
__device__ float d_inv [2 * BATCH * CIN];

__device__ __forceinline__ float relu6f(float x) { return fminf(fmaxf(x, 0.0f), 6.0f); }
__device__ __forceinline__ float tf32rna(float x) {
    float r; asm("cvt.rna.tf32.f32 %0, %1;" : "=f"(r) : "f"(x)); return r;
}
// m16n8k8 tf32 MMA (baseline PTX, sm_80+)
__device__ __forceinline__ void mma8(float* d, const uint32_t* a, const uint32_t* b) {
    asm volatile("mma.sync.aligned.m16n8k8.row.col.f32.tf32.tf32.f32 "
                 "{%0,%1,%2,%3},{%4,%5,%6,%7},{%8,%9},{%0,%1,%2,%3};"
                 : "+f"(d[0]), "+f"(d[1]), "+f"(d[2]), "+f"(d[3])
                 : "r"(a[0]), "r"(a[1]), "r"(a[2]), "r"(a[3]), "r"(b[0]), "r"(b[1]));
}

// ---------------- per-(b,c) instance-norm stats, ddof=1 ----------------
__global__ __launch_bounds__(256) void stats_kernel(const float* __restrict__ Fc,
                                                    const float* __restrict__ Fs) {
    int inst  = blockIdx.x;
    int which = blockIdx.y;
    const float* src = (which ? Fs : Fc) + (size_t)inst * NT;
    int tid = threadIdx.x;
    float s = 0.f, ss = 0.f;
    for (int e = tid; e < NT / 4; e += 256) {
        float4 v = ((const float4*)src)[e];
        s  += v.x + v.y + v.z + v.w;
        ss += v.x * v.x + v.y * v.y + v.z * v.z + v.w * v.w;
    }
    for (int o = 16; o; o >>= 1) {
        s  += __shfl_xor_sync(0xffffffffu, s, o);
        ss += __shfl_xor_sync(0xffffffffu, ss, o);
    }
    __shared__ float sb[8], ssb[8];
    if ((tid & 31) == 0) { sb[tid >> 5] = s; ssb[tid >> 5] = ss; }
    __syncthreads();
    if (tid == 0) {
        s = 0.f; ss = 0.f;
        for (int w = 0; w < 8; w++) { s += sb[w]; ss += ssb[w]; }
        float mean = s / (float)NT;
        float var  = (ss - s * mean) / (float)(NT - 1);
        d_mean[which * BATCH * CIN + inst] = mean;
        d_inv [which * BATCH * CIN + inst] = rsqrtf(var + 1e-5f);
    }
}

// ---------------- tf32 mma.sync GEMM: C[M,N] = A[M,K] * B[N,K]^T (+bias, relu6) ---
// CTA tile 128x128, K-chunk 32, 8 warps (32x64 warp tile), reg-prefetch pipeline.
template<int SPLIT, int ACT>
__global__ __launch_bounds__(256, 1)
void mma_gemm(const float* __restrict__ Ag, const float* __restrict__ Bg,
              const float* __restrict__ bias, float* __restrict__ Cg,
              int K, int lda, int ldb, int ldc,
              size_t bA, size_t bB, size_t bC)
{
    constexpr int SROW = SPLIT ? 68 : 36;   // ≡4 mod 32 -> conflict-free fragment reads
    extern __shared__ float smf[];
    float* SA = smf;
    float* SB = smf + 128 * SROW;
    const uint32_t* UA = (const uint32_t*)SA;
    const uint32_t* UB = (const uint32_t*)SB;

    const int tid  = threadIdx.x;
    const int wid  = tid >> 5, lane = tid & 31;
    const int wm   = wid & 3,  wn   = wid >> 2;
    const int lr   = lane >> 2, lc  = lane & 3;
    const int rbase = tid >> 3;
    const int c4    = (tid & 7) * 4;

    const float* A = Ag + blockIdx.z * bA + (size_t)(blockIdx.y * 128) * lda;
    const float* B = Bg + blockIdx.z * bB + (size_t)(blockIdx.x * 128) * ldb;
    float*       C = Cg + blockIdx.z * bC + (size_t)(blockIdx.y * 128) * ldc + blockIdx.x * 128;

    float acc[2][8][4];
#pragma unroll
    for (int mi = 0; mi < 2; mi++)
#pragma unroll
        for (int nj = 0; nj < 8; nj++)
#pragma unroll
            for (int q = 0; q < 4; q++) acc[mi][nj][q] = 0.f;

    float4 pa[4], pb[4];
#pragma unroll
    for (int i = 0; i < 4; i++) {
        pa[i] = *(const float4*)(A + (size_t)(rbase + 32 * i) * lda + c4);
        pb[i] = *(const float4*)(B + (size_t)(rbase + 32 * i) * ldb + c4);
    }

    const int NCH = K / 32;
    for (int c = 0; c < NCH; c++) {
#pragma unroll
        for (int i = 0; i < 4; i++) {
            int r = rbase + 32 * i;
            if (SPLIT) {
                float4 hi, lo;
                hi.x = tf32rna(pa[i].x); lo.x = pa[i].x - hi.x;
                hi.y = tf32rna(pa[i].y); lo.y = pa[i].y - hi.y;
                hi.z = tf32rna(pa[i].z); lo.z = pa[i].z - hi.z;
                hi.w = tf32rna(pa[i].w); lo.w = pa[i].w - hi.w;
                *(float4*)(SA + r * SROW + c4)      = hi;
                *(float4*)(SA + r * SROW + 32 + c4) = lo;
                hi.x = tf32rna(pb[i].x); lo.x = pb[i].x - hi.x;
                hi.y = tf32rna(pb[i].y); lo.y = pb[i].y - hi.y;
                hi.z = tf32rna(pb[i].z); lo.z = pb[i].z - hi.z;
                hi.w = tf32rna(pb[i].w); lo.w = pb[i].w - hi.w;
                *(float4*)(SB + r * SROW + c4)      = hi;
                *(float4*)(SB + r * SROW + 32 + c4) = lo;
            } else {
                float4 v = pa[i];
                v.x = tf32rna(v.x); v.y = tf32rna(v.y);
                v.z = tf32rna(v.z); v.w = tf32rna(v.w);
                *(float4*)(SA + r * SROW + c4) = v;
                v = pb[i];
                v.x = tf32rna(v.x); v.y = tf32rna(v.y);
                v.z = tf32rna(v.z); v.w = tf32rna(v.w);
                *(float4*)(SB + r * SROW + c4) = v;
            }
        }
        __syncthreads();
        if (c + 1 < NCH) {
#pragma unroll
            for (int i = 0; i < 4; i++) {
                pa[i] = *(const float4*)(A + (size_t)(rbase + 32 * i) * lda + (c + 1) * 32 + c4);
                pb[i] = *(const float4*)(B + (size_t)(rbase + 32 * i) * ldb + (c + 1) * 32 + c4);
            }
        }
#pragma unroll
        for (int ks = 0; ks < 4; ks++) {
            const int k0 = ks * 8;
            uint32_t ah[2][4], bh[8][2];
#pragma unroll
            for (int mi = 0; mi < 2; mi++) {
                int base = (wm * 32 + mi * 16 + lr) * SROW + k0 + lc;
                ah[mi][0] = UA[base];            ah[mi][1] = UA[base + 8 * SROW];
                ah[mi][2] = UA[base + 4];        ah[mi][3] = UA[base + 8 * SROW + 4];
            }
#pragma unroll
            for (int nj = 0; nj < 8; nj++) {
                int base = (wn * 64 + nj * 8 + lr) * SROW + k0 + lc;
                bh[nj][0] = UB[base];            bh[nj][1] = UB[base + 4];
            }
#pragma unroll
            for (int mi = 0; mi < 2; mi++)
#pragma unroll
                for (int nj = 0; nj < 8; nj++)
                    mma8(acc[mi][nj], ah[mi], bh[nj]);
            if (SPLIT) {
                uint32_t al[2][4], bl[8][2];
#pragma unroll
                for (int mi = 0; mi < 2; mi++) {
                    int base = (wm * 32 + mi * 16 + lr) * SROW + 32 + k0 + lc;
                    al[mi][0] = UA[base];        al[mi][1] = UA[base + 8 * SROW];
                    al[mi][2] = UA[base + 4];    al[mi][3] = UA[base + 8 * SROW + 4];
                }
#pragma unroll
                for (int nj = 0; nj < 8; nj++) {
                    int base = (wn * 64 + nj * 8 + lr) * SROW + 32 + k0 + lc;
                    bl[nj][0] = UB[base];        bl[nj][1] = UB[base + 4];
                }
#pragma unroll
                for (int mi = 0; mi < 2; mi++)
#pragma unroll
                    for (int nj = 0; nj < 8; nj++) {
                        mma8(acc[mi][nj], ah[mi], bl[nj]);
                        mma8(acc[mi][nj], al[mi], bh[nj]);
                    }
            }
        }
        __syncthreads();
    }

#pragma unroll
    for (int mi = 0; mi < 2; mi++) {
        int r = wm * 32 + mi * 16 + lr;
        float b0 = 0.f, b1 = 0.f;
        if (ACT) {
            b0 = bias[blockIdx.y * 128 + r];
            b1 = bias[blockIdx.y * 128 + r + 8];
        }
#pragma unroll
        for (int nj = 0; nj < 8; nj++) {
            int col = wn * 64 + nj * 8 + lc * 2;
            float2 v0 = make_float2(acc[mi][nj][0], acc[mi][nj][1]);
            float2 v1 = make_float2(acc[mi][nj][2], acc[mi][nj][3]);
            if (ACT) {
                v0.x = relu6f(v0.x + b0); v0.y = relu6f(v0.y + b0);
                v1.x = relu6f(v1.x + b1); v1.y = relu6f(v1.y + b1);
            }
            *(float2*)(C + (size_t)r * ldc + col)       = v0;
            *(float2*)(C + (size_t)(r + 8) * ldc + col) = v1;
        }
    }
}

// ---------------- tensor-core 1x1 conv: C = relu6(W @ X + bias) -------------------
// A = W[r][k] row-major; B = X[k][n] (k-major gmem) read via [k][n] smem tile.
// Optional instance-norm of X. TRANSOUT=1 -> write C[n][r] (smem-staged transpose).
template<int SPLIT, int TRANSOUT>
__global__ __launch_bounds__(256, 1)
void conv_mma(const float* __restrict__ Wg, const float* __restrict__ Xg,
              const float* __restrict__ bias,
              const float* __restrict__ mean, const float* __restrict__ inv,
              float* __restrict__ Cg, int K, int ldc, size_t bC)
{
    constexpr int SROW = SPLIT ? 68 : 36;
    extern __shared__ float smf[];
    float* SA  = smf;                              // W tile [128r][SROW]
    float* XS0 = smf + 128 * SROW;                 // X tile hi [32k][132]
    float* XS1 = XS0 + (SPLIT ? 32 * 132 : 0);     // X tile lo
    float* stage = smf;                            // epilogue overlay [128n][132]
    const uint32_t* UA  = (const uint32_t*)SA;
    const uint32_t* UX0 = (const uint32_t*)XS0;
    const uint32_t* UX1 = (const uint32_t*)XS1;

    const int tid  = threadIdx.x;
    const int wid  = tid >> 5, lane = tid & 31;
    const int wm   = wid & 3,  wn   = wid >> 4 ? 1 : (wid >> 2);  // placeholder fix below
    const int wn2  = wid >> 2;
    const int lr   = lane >> 2, lc  = lane & 3;
    const int rbase = tid >> 3;
    const int c4    = (tid & 7) * 4;
    const int kk    = tid >> 5;          // 0..7 (k row group for X loads)
    const int n4    = (tid & 31) * 4;

    const int b  = blockIdx.z;
    const int n0 = blockIdx.x * 128;
    const int r0 = blockIdx.y * 128;
    const float* X = Xg + (size_t)b * K * NT;
    const float* mu = mean ? mean + b * K : nullptr;
    const float* iv = inv  ? inv  + b * K : nullptr;
    float* C = Cg + b * bC;

    float acc[2][8][4];
#pragma unroll
    for (int mi = 0; mi < 2; mi++)
#pragma unroll
        for (int nj = 0; nj < 8; nj++)
#pragma unroll
            for (int q = 0; q < 4; q++) acc[mi][nj][q] = 0.f;

    float4 pa[4], px[4];
    float pm[4], pv[4];
#pragma unroll
    for (int i = 0; i < 4; i++) {
        pa[i] = *(const float4*)(Wg + (size_t)(r0 + rbase + 32 * i) * K + c4);
        int k = kk + 8 * i;
        px[i] = *(const float4*)(X + (size_t)k * NT + n0 + n4);
        pm[i] = mu ? mu[k] : 0.f;
        pv[i] = iv ? iv[k] : 1.f;
    }

    const int NCH = K / 32;
    for (int c = 0; c < NCH; c++) {
        // store W tile
#pragma unroll
        for (int i = 0; i < 4; i++) {
            int r = rbase + 32 * i;
            if (SPLIT) {
                float4 hi, lo;
                hi.x = tf32rna(pa[i].x); lo.x = pa[i].x - hi.x;
                hi.y = tf32rna(pa[i].y); lo.y = pa[i].y - hi.y;
                hi.z = tf32rna(pa[i].z); lo.z = pa[i].z - hi.z;
                hi.w = tf32rna(pa[i].w); lo.w = pa[i].w - hi.w;
                *(float4*)(SA + r * SROW + c4)      = hi;
                *(float4*)(SA + r * SROW + 32 + c4) = lo;
            } else {
                float4 v = pa[i];
                v.x = tf32rna(v.x); v.y = tf32rna(v.y);
                v.z = tf32rna(v.z); v.w = tf32rna(v.w);
                *(float4*)(SA + r * SROW + c4) = v;
            }
        }
        // store X tile (normalized), [k][n] layout
#pragma unroll
        for (int i = 0; i < 4; i++) {
            int k = kk + 8 * i;
            float4 v = px[i];
            v.x = (v.x - pm[i]) * pv[i]; v.y = (v.y - pm[i]) * pv[i];
            v.z = (v.z - pm[i]) * pv[i]; v.w = (v.w - pm[i]) * pv[i];
            if (SPLIT) {
                float4 hi, lo;
                hi.x = tf32rna(v.x); lo.x = v.x - hi.x;
                hi.y = tf32rna(v.y); lo.y = v.y - hi.y;
                hi.z = tf32rna(v.z); lo.z = v.z - hi.z;
                hi.w = tf32rna(v.w); lo.w = v.w - hi.w;
                *(float4*)(XS0 + k * 132 + n4) = hi;
                *(float4*)(XS1 + k * 132 + n4) = lo;
            } else {
                v.x = tf32rna(v.x); v.y = tf32rna(v.y);
                v.z = tf32rna(v.z); v.w = tf32rna(v.w);
                *(float4*)(XS0 + k * 132 + n4) = v;
            }
        }
        __syncthreads();
        if (c + 1 < NCH) {
#pragma unroll
            for (int i = 0; i < 4; i++) {
                pa[i] = *(const float4*)(Wg + (size_t)(r0 + rbase + 32 * i) * K + (c + 1) * 32 + c4);
                int k = (c + 1) * 32 + kk + 8 * i;
                px[i] = *(const float4*)(X + (size_t)k * NT + n0 + n4);
                pm[i] = mu ? mu[k] : 0.f;
                pv[i] = iv ? iv[k] : 1.f;
            }
        }
#pragma unroll
        for (int ks = 0; ks < 4; ks++) {
            const int k0 = ks * 8;
            uint32_t ah[2][4], bh[8][2];
#pragma unroll
            for (int mi = 0; mi < 2; mi++) {
                int base = (wm * 32 + mi * 16 + lr) * SROW + k0 + lc;
                ah[mi][0] = UA[base];            ah[mi][1] = UA[base + 8 * SROW];
                ah[mi][2] = UA[base + 4];        ah[mi][3] = UA[base + 8 * SROW + 4];
            }
#pragma unroll
            for (int nj = 0; nj < 8; nj++) {
                int col = wn2 * 64 + nj * 8 + lr;
                bh[nj][0] = UX0[(k0 + lc) * 132 + col];
                bh[nj][1] = UX0[(k0 + lc + 4) * 132 + col];
            }
#pragma unroll
            for (int mi = 0; mi < 2; mi++)
#pragma unroll
                for (int nj = 0; nj < 8; nj++)
                    mma8(acc[mi][nj], ah[mi], bh[nj]);
            if (SPLIT) {
                uint32_t al[2][4], bl[8][2];
#pragma unroll
                for (int mi = 0; mi < 2; mi++) {
                    int base = (wm * 32 + mi * 16 + lr) * SROW + 32 + k0 + lc;
                    al[mi][0] = UA[base];        al[mi][1] = UA[base + 8 * SROW];
                    al[mi][2] = UA[base + 4];    al[mi][3] = UA[base + 8 * SROW + 4];
                }
#pragma unroll
                for (int nj = 0; nj < 8; nj++) {
                    int col = wn2 * 64 + nj * 8 + lr;
                    bl[nj][0] = UX1[(k0 + lc) * 132 + col];
                    bl[nj][1] = UX1[(k0 + lc + 4) * 132 + col];
                }
#pragma unroll
                for (int mi = 0; mi < 2; mi++)
#pragma unroll
                    for (int nj = 0; nj < 8; nj++) {
                        mma8(acc[mi][nj], ah[mi], bl[nj]);
                        mma8(acc[mi][nj], al[mi], bh[nj]);
                    }
            }
        }
        __syncthreads();
    }

    if (!TRANSOUT) {
        // C[r][n], ldc = NT
#pragma unroll
        for (int mi = 0; mi < 2; mi++) {
            int r = wm * 32 + mi * 16 + lr;
            float b0 = bias[r0 + r], b1 = bias[r0 + r + 8];
#pragma unroll
            for (int nj = 0; nj < 8; nj++) {
                int col = wn2 * 64 + nj * 8 + lc * 2;
                float2 v0 = make_float2(relu6f(acc[mi][nj][0] + b0),
                                        relu6f(acc[mi][nj][1] + b0));
                float2 v1 = make_float2(relu6f(acc[mi][nj][2] + b1),
                                        relu6f(acc[mi][nj][3] + b1));
                *(float2*)(C + (size_t)(r0 + r) * ldc + n0 + col)     = v0;
                *(float2*)(C + (size_t)(r0 + r + 8) * ldc + n0 + col) = v1;
            }
        }
    } else {
        // stage transposed, then write C[n][r], ldc = R
#pragma unroll
        for (int mi = 0; mi < 2; mi++) {
            int r = wm * 32 + mi * 16 + lr;
            float b0 = bias[r0 + r], b1 = bias[r0 + r + 8];
#pragma unroll
            for (int nj = 0; nj < 8; nj++) {
                int nl = wn2 * 64 + nj * 8 + lc * 2;
                stage[(size_t)nl * 132 + r]           = relu6f(acc[mi][nj][0] + b0);
                stage[(size_t)(nl + 1) * 132 + r]     = relu6f(acc[mi][nj][1] + b0);
                stage[(size_t)nl * 132 + r + 8]       = relu6f(acc[mi][nj][2] + b1);
                stage[(size_t)(nl + 1) * 132 + r + 8] = relu6f(acc[mi][nj][3] + b1);
            }
        }
        __syncthreads();
#pragma unroll
        for (int i = 0; i < 16; i++) {
            int e = tid + i * 256;
            int n = e >> 5, r4 = (e & 31) * 4;
            *(float4*)(C + (size_t)(n0 + n) * ldc + r0 + r4) = *(const float4*)(stage + n * 132 + r4);
        }
    }
}

// ---------------- row softmax over m (in-place on S), 4096 per row ----------------
__global__ __launch_bounds__(256) void softmax_kernel(float* __restrict__ S) {
    float* p = S + (size_t)blockIdx.x * NT;
    int tid = threadIdx.x;
    float4 v[4];
    float mx = -1e30f;
#pragma unroll
    for (int i = 0; i < 4; i++) {
        v[i] = ((const float4*)p)[tid + i * 256];
        mx = fmaxf(mx, fmaxf(fmaxf(v[i].x, v[i].y), fmaxf(v[i].z, v[i].w)));
    }
    __shared__ float redm[8], reds[8];
#pragma unroll
    for (int o = 16; o; o >>= 1) mx = fmaxf(mx, __shfl_xor_sync(0xffffffffu, mx, o));
    if ((tid & 31) == 0) redm[tid >> 5] = mx;
    __syncthreads();
    mx = fmaxf(fmaxf(fmaxf(redm[0], redm[1]), fmaxf(redm[2], redm[3])),
               fmaxf(fmaxf(redm[4], redm[5]), fmaxf(redm[6], redm[7])));
    float s = 0.f;
#pragma unroll
    for (int i = 0; i < 4; i++) {
        v[i].x = __expf(v[i].x - mx); v[i].y = __expf(v[i].y - mx);
        v[i].z = __expf(v[i].z - mx); v[i].w = __expf(v[i].w - mx);
        s += v[i].x + v[i].y + v[i].z + v[i].w;
    }
#pragma unroll
    for (int o = 16; o; o >>= 1) s += __shfl_xor_sync(0xffffffffu, s, o);
    if ((tid & 31) == 0) reds[tid >> 5] = s;
    __syncthreads();
    s = reds[0] + reds[1] + reds[2] + reds[3] + reds[4] + reds[5] + reds[6] + reds[7];
    float inv = 1.f / s;
#pragma unroll
    for (int i = 0; i < 4; i++) {
        v[i].x *= inv; v[i].y *= inv; v[i].z *= inv; v[i].w *= inv;
        ((float4*)p)[tid + i * 256] = v[i];
    }
}

// ---------------- launch ----------------
extern "C" void kernel_launch(void* const* d_in, const int* in_sizes, int n_in,
                              void* d_out, int out_size) {
    const float* Fc    = (const float*)d_in[0];
    const float* Fs    = (const float*)d_in[1];
    const float* f_w   = (const float*)d_in[2];
    const float* f_b   = (const float*)d_in[3];
    const float* g_w   = (const float*)d_in[4];
    const float* g_b   = (const float*)d_in[5];
    const float* h_w   = (const float*)d_in[6];
    const float* h_b   = (const float*)d_in[7];
    const float* out_w = (const float*)d_in[8];
    const float* out_b = (const float*)d_in[9];
    float* out = (float*)d_out;

    float *pfT, *pgT, *ph, *pfcs, *pS, *pmean, *pinv;
    cudaGetSymbolAddress((void**)&pfT,   d_fT);
    cudaGetSymbolAddress((void**)&pgT,   d_gT);
    cudaGetSymbolAddress((void**)&ph,    d_h);
    cudaGetSymbolAddress((void**)&pfcs,  d_fcs);
    cudaGetSymbolAddress((void**)&pS,    d_S);
    cudaGetSymbolAddress((void**)&pmean, d_mean);
    cudaGetSymbolAddress((void**)&pinv,  d_inv);

    const int SM_G1 = 2 * 128 * 68 * 4;                 // 69632 (split gemm)
    const int SM_G0 = 2 * 128 * 36 * 4;                 // 36864
    const int SM_C1 = (128 * 68 + 2 * 32 * 132) * 4;    // 68608 (split conv, >= stage 67584)
    const int SM_C0 = (128 * 36 + 32 * 132) * 4;        // 35328
    cudaFuncSetAttribute(mma_gemm<1, 0>, cudaFuncAttributeMaxDynamicSharedMemorySize, SM_G1);
    cudaFuncSetAttribute(mma_gemm<0, 0>, cudaFuncAttributeMaxDynamicSharedMemorySize, SM_G0);
    cudaFuncSetAttribute(mma_gemm<0, 1>, cudaFuncAttributeMaxDynamicSharedMemorySize, SM_G0);
    cudaFuncSetAttribute(conv_mma<1, 1>, cudaFuncAttributeMaxDynamicSharedMemorySize, SM_C1);
    cudaFuncSetAttribute(conv_mma<0, 0>, cudaFuncAttributeMaxDynamicSharedMemorySize, SM_C0);

    stats_kernel<<<dim3(BATCH * CIN, 2), 256>>>(Fc, Fs);

    // fT[n][d] = relu6(f_w @ mvn(Fc) + f_b)^T   (3xtf32)
    conv_mma<1, 1><<<dim3(NT / 128, CH / 128, BATCH), 256, SM_C1>>>(
        f_w, Fc, f_b, pmean, pinv, pfT, CIN, CH, (size_t)NT * CH);
    // gT[m][d] = relu6(g_w @ mvn(Fs) + g_b)^T   (3xtf32)
    conv_mma<1, 1><<<dim3(NT / 128, CH / 128, BATCH), 256, SM_C1>>>(
        g_w, Fs, g_b, pmean + BATCH * CIN, pinv + BATCH * CIN, pgT, CIN, CH, (size_t)NT * CH);
    // h[d][m] = relu6(h_w @ Fs + h_b)           (1xtf32)
    conv_mma<0, 0><<<dim3(NT / 128, CH / 128, BATCH), 256, SM_C0>>>(
        h_w, Fs, h_b, nullptr, nullptr, ph, CIN, NT, (size_t)CH * NT);

    // S[n][m] = fT . gT^T   (3xtf32)
    mma_gemm<1, 0><<<dim3(NT / 128, NT / 128, BATCH), 256, SM_G1>>>(
        pfT, pgT, nullptr, pS, CH, CH, CH, NT,
        (size_t)NT * CH, (size_t)NT * CH, (size_t)NT * NT);

    // P = softmax_m(S), in place
    softmax_kernel<<<BATCH * NT, 256>>>(pS);

    // fcs[n][d] = P . h^T   (1xtf32)
    mma_gemm<0, 0><<<dim3(CH / 128, NT / 128, BATCH), 256, SM_G0>>>(
        pS, ph, nullptr, pfcs, NT, NT, NT, CH,
        (size_t)NT * NT, (size_t)CH * NT, (size_t)NT * CH);

    // out[r][n] = relu6(out_w @ fcs^T + out_b)  (1xtf32)
    mma_gemm<0, 1><<<dim3(NT / 128, CIN / 128, BATCH), 256, SM_G0>>>(
        out_w, pfcs, out_b, out, CH, CH, CH, NT,
        (size_t)0, (size_t)NT * CH, (size_t)CIN * NT);
}

// round 13
// speedup vs baseline: 1.0390x; 1.0390x over previous
#include <cuda_runtime.h>
#include <cstdint>
#include <cstddef>

#define NT    4096      // H*W tokens
#define CH    256       // hidden channels
#define CIN   512       // input channels
#define BATCH 4

// ---------------- scratch (device globals; no allocation in kernel_launch) --------
__device__ float d_fT [(size_t)BATCH * NT * CH];   // fT [b][n][d]
__device__ float d_gT [(size_t)BATCH * NT * CH];   // gT [b][m][d]
__device__ float d_h  [(size_t)BATCH * CH * NT];   // h  [b][d][m]
__device__ float d_fcs[(size_t)BATCH * NT * CH];   // Fcs[b][n][d]
__device__ float d_S  [(size_t)BATCH * NT * NT];   // scores [b][n][m]
__device__ float d_soff[(size_t)BATCH * NT];       // per-row max + ln(sum)
__device__ float d_mean[2 * BATCH * CIN];
__device__ float d_inv [2 * BATCH * CIN];

__device__ __forceinline__ float relu6f(float x) { return fminf(fmaxf(x, 0.0f), 6.0f); }
__device__ __forceinline__ float tf32rna(float x) {
    float r; asm("cvt.rna.tf32.f32 %0, %1;" : "=f"(r) : "f"(x)); return r;
}
// m16n8k8 tf32 MMA (baseline PTX, sm_80+)
__device__ __forceinline__ void mma8(float* d, const uint32_t* a, const uint32_t* b) {
    asm volatile("mma.sync.aligned.m16n8k8.row.col.f32.tf32.tf32.f32 "
                 "{%0,%1,%2,%3},{%4,%5,%6,%7},{%8,%9},{%0,%1,%2,%3};"
                 : "+f"(d[0]), "+f"(d[1]), "+f"(d[2]), "+f"(d[3])
                 : "r"(a[0]), "r"(a[1]), "r"(a[2]), "r"(a[3]), "r"(b[0]), "r"(b[1]));
}

// ---------------- per-(b,c) instance-norm stats, ddof=1 ----------------
__global__ __launch_bounds__(256) void stats_kernel(const float* __restrict__ Fc,
                                                    const float* __restrict__ Fs) {
    int inst  = blockIdx.x;
    int which = blockIdx.y;
    const float* src = (which ? Fs : Fc) + (size_t)inst * NT;
    int tid = threadIdx.x;
    float s = 0.f, ss = 0.f;
    for (int e = tid; e < NT / 4; e += 256) {
        float4 v = ((const float4*)src)[e];
        s  += v.x + v.y + v.z + v.w;
        ss += v.x * v.x + v.y * v.y + v.z * v.z + v.w * v.w;
    }
    for (int o = 16; o; o >>= 1) {
        s  += __shfl_xor_sync(0xffffffffu, s, o);
        ss += __shfl_xor_sync(0xffffffffu, ss, o);
    }
    __shared__ float sb[8], ssb[8];
    if ((tid & 31) == 0) { sb[tid >> 5] = s; ssb[tid >> 5] = ss; }
    __syncthreads();
    if (tid == 0) {
        s = 0.f; ss = 0.f;
        for (int w = 0; w < 8; w++) { s += sb[w]; ss += ssb[w]; }
        float mean = s / (float)NT;
        float var  = (ss - s * mean) / (float)(NT - 1);
        d_mean[which * BATCH * CIN + inst] = mean;
        d_inv [which * BATCH * CIN + inst] = rsqrtf(var + 1e-5f);
    }
}

// ---------------- tf32 mma.sync GEMM: C[M,N] = A[M,K] * B[N,K]^T -----------------
// CTA tile 128x128, K-chunk 32, 8 warps (32x64 warp tile).
// Double-buffered smem (one __syncthreads per chunk) + global reg prefetch.
// EXPA=1: A values transformed p = exp(a - aoff[row]) at smem-store time.
template<int SPLIT, int ACT, int EXPA>
__global__ __launch_bounds__(256, 1)
void mma_gemm(const float* __restrict__ Ag, const float* __restrict__ Bg,
              const float* __restrict__ bias, const float* __restrict__ aoffg,
              float* __restrict__ Cg,
              int K, int lda, int ldb, int ldc,
              size_t bA, size_t bB, size_t bC)
{
    constexpr int SROW = SPLIT ? 68 : 36;   // ≡4 mod 32 -> conflict-free fragment reads
    constexpr int TBUF = 128 * SROW;
    extern __shared__ float smf[];
    float* SAbase = smf;                 // 2 x TBUF
    float* SBbase = smf + 2 * TBUF;      // 2 x TBUF

    const int tid  = threadIdx.x;
    const int wid  = tid >> 5, lane = tid & 31;
    const int wm   = wid & 3,  wn   = wid >> 2;
    const int lr   = lane >> 2, lc  = lane & 3;
    const int rbase = tid >> 3;
    const int c4    = (tid & 7) * 4;

    const float* A = Ag + blockIdx.z * bA + (size_t)(blockIdx.y * 128) * lda;
    const float* B = Bg + blockIdx.z * bB + (size_t)(blockIdx.x * 128) * ldb;
    float*       C = Cg + blockIdx.z * bC + (size_t)(blockIdx.y * 128) * ldc + blockIdx.x * 128;

    float acc[2][8][4];
#pragma unroll
    for (int mi = 0; mi < 2; mi++)
#pragma unroll
        for (int nj = 0; nj < 8; nj++)
#pragma unroll
            for (int q = 0; q < 4; q++) acc[mi][nj][q] = 0.f;

    float po[4];
    if (EXPA) {
        const float* Ao = aoffg + blockIdx.z * NT + blockIdx.y * 128;
#pragma unroll
        for (int i = 0; i < 4; i++) po[i] = Ao[rbase + 32 * i];
    }

    float4 pa[4], pb[4];
#pragma unroll
    for (int i = 0; i < 4; i++) {
        pa[i] = *(const float4*)(A + (size_t)(rbase + 32 * i) * lda + c4);
        pb[i] = *(const float4*)(B + (size_t)(rbase + 32 * i) * ldb + c4);
    }

    const int NCH = K / 32;

    // store chunk 0 into buffer 0
    {
        float* SA = SAbase; float* SB = SBbase;
#pragma unroll
        for (int i = 0; i < 4; i++) {
            int r = rbase + 32 * i;
            if (SPLIT) {
                float4 hi, lo;
                hi.x = tf32rna(pa[i].x); lo.x = pa[i].x - hi.x;
                hi.y = tf32rna(pa[i].y); lo.y = pa[i].y - hi.y;
                hi.z = tf32rna(pa[i].z); lo.z = pa[i].z - hi.z;
                hi.w = tf32rna(pa[i].w); lo.w = pa[i].w - hi.w;
                *(float4*)(SA + r * SROW + c4)      = hi;
                *(float4*)(SA + r * SROW + 32 + c4) = lo;
                hi.x = tf32rna(pb[i].x); lo.x = pb[i].x - hi.x;
                hi.y = tf32rna(pb[i].y); lo.y = pb[i].y - hi.y;
                hi.z = tf32rna(pb[i].z); lo.z = pb[i].z - hi.z;
                hi.w = tf32rna(pb[i].w); lo.w = pb[i].w - hi.w;
                *(float4*)(SB + r * SROW + c4)      = hi;
                *(float4*)(SB + r * SROW + 32 + c4) = lo;
            } else {
                float4 v = pa[i];
                if (EXPA) {
                    v.x = __expf(v.x - po[i]); v.y = __expf(v.y - po[i]);
                    v.z = __expf(v.z - po[i]); v.w = __expf(v.w - po[i]);
                }
                v.x = tf32rna(v.x); v.y = tf32rna(v.y);
                v.z = tf32rna(v.z); v.w = tf32rna(v.w);
                *(float4*)(SA + r * SROW + c4) = v;
                v = pb[i];
                v.x = tf32rna(v.x); v.y = tf32rna(v.y);
                v.z = tf32rna(v.z); v.w = tf32rna(v.w);
                *(float4*)(SB + r * SROW + c4) = v;
            }
        }
    }
    __syncthreads();

    for (int c = 0; c < NCH; c++) {
        const int cur = c & 1;
        const bool more = (c + 1 < NCH);
        if (more) {
#pragma unroll
            for (int i = 0; i < 4; i++) {
                pa[i] = *(const float4*)(A + (size_t)(rbase + 32 * i) * lda + (c + 1) * 32 + c4);
                pb[i] = *(const float4*)(B + (size_t)(rbase + 32 * i) * ldb + (c + 1) * 32 + c4);
            }
        }
        const uint32_t* UA = (const uint32_t*)(SAbase + cur * TBUF);
        const uint32_t* UB = (const uint32_t*)(SBbase + cur * TBUF);
#pragma unroll
        for (int ks = 0; ks < 4; ks++) {
            const int k0 = ks * 8;
            uint32_t ah[2][4], bh[8][2];
#pragma unroll
            for (int mi = 0; mi < 2; mi++) {
                int base = (wm * 32 + mi * 16 + lr) * SROW + k0 + lc;
                ah[mi][0] = UA[base];            ah[mi][1] = UA[base + 8 * SROW];
                ah[mi][2] = UA[base + 4];        ah[mi][3] = UA[base + 8 * SROW + 4];
            }
#pragma unroll
            for (int nj = 0; nj < 8; nj++) {
                int base = (wn * 64 + nj * 8 + lr) * SROW + k0 + lc;
                bh[nj][0] = UB[base];            bh[nj][1] = UB[base + 4];
            }
#pragma unroll
            for (int mi = 0; mi < 2; mi++)
#pragma unroll
                for (int nj = 0; nj < 8; nj++)
                    mma8(acc[mi][nj], ah[mi], bh[nj]);
            if (SPLIT) {
                uint32_t al[2][4], bl[8][2];
#pragma unroll
                for (int mi = 0; mi < 2; mi++) {
                    int base = (wm * 32 + mi * 16 + lr) * SROW + 32 + k0 + lc;
                    al[mi][0] = UA[base];        al[mi][1] = UA[base + 8 * SROW];
                    al[mi][2] = UA[base + 4];    al[mi][3] = UA[base + 8 * SROW + 4];
                }
#pragma unroll
                for (int nj = 0; nj < 8; nj++) {
                    int base = (wn * 64 + nj * 8 + lr) * SROW + 32 + k0 + lc;
                    bl[nj][0] = UB[base];        bl[nj][1] = UB[base + 4];
                }
#pragma unroll
                for (int mi = 0; mi < 2; mi++)
#pragma unroll
                    for (int nj = 0; nj < 8; nj++) {
                        mma8(acc[mi][nj], ah[mi], bl[nj]);
                        mma8(acc[mi][nj], al[mi], bh[nj]);
                    }
            }
        }
        if (more) {
            float* SA = SAbase + (cur ^ 1) * TBUF;
            float* SB = SBbase + (cur ^ 1) * TBUF;
#pragma unroll
            for (int i = 0; i < 4; i++) {
                int r = rbase + 32 * i;
                if (SPLIT) {
                    float4 hi, lo;
                    hi.x = tf32rna(pa[i].x); lo.x = pa[i].x - hi.x;
                    hi.y = tf32rna(pa[i].y); lo.y = pa[i].y - hi.y;
                    hi.z = tf32rna(pa[i].z); lo.z = pa[i].z - hi.z;
                    hi.w = tf32rna(pa[i].w); lo.w = pa[i].w - hi.w;
                    *(float4*)(SA + r * SROW + c4)      = hi;
                    *(float4*)(SA + r * SROW + 32 + c4) = lo;
                    hi.x = tf32rna(pb[i].x); lo.x = pb[i].x - hi.x;
                    hi.y = tf32rna(pb[i].y); lo.y = pb[i].y - hi.y;
                    hi.z = tf32rna(pb[i].z); lo.z = pb[i].z - hi.z;
                    hi.w = tf32rna(pb[i].w); lo.w = pb[i].w - hi.w;
                    *(float4*)(SB + r * SROW + c4)      = hi;
                    *(float4*)(SB + r * SROW + 32 + c4) = lo;
                } else {
                    float4 v = pa[i];
                    if (EXPA) {
                        v.x = __expf(v.x - po[i]); v.y = __expf(v.y - po[i]);
                        v.z = __expf(v.z - po[i]); v.w = __expf(v.w - po[i]);
                    }
                    v.x = tf32rna(v.x); v.y = tf32rna(v.y);
                    v.z = tf32rna(v.z); v.w = tf32rna(v.w);
                    *(float4*)(SA + r * SROW + c4) = v;
                    v = pb[i];
                    v.x = tf32rna(v.x); v.y = tf32rna(v.y);
                    v.z = tf32rna(v.z); v.w = tf32rna(v.w);
                    *(float4*)(SB + r * SROW + c4) = v;
                }
            }
        }
        __syncthreads();
    }

#pragma unroll
    for (int mi = 0; mi < 2; mi++) {
        int r = wm * 32 + mi * 16 + lr;
        float b0 = 0.f, b1 = 0.f;
        if (ACT) {
            b0 = bias[blockIdx.y * 128 + r];
            b1 = bias[blockIdx.y * 128 + r + 8];
        }
#pragma unroll
        for (int nj = 0; nj < 8; nj++) {
            int col = wn * 64 + nj * 8 + lc * 2;
            float2 v0 = make_float2(acc[mi][nj][0], acc[mi][nj][1]);
            float2 v1 = make_float2(acc[mi][nj][2], acc[mi][nj][3]);
            if (ACT) {
                v0.x = relu6f(v0.x + b0); v0.y = relu6f(v0.y + b0);
                v1.x = relu6f(v1.x + b1); v1.y = relu6f(v1.y + b1);
            }
            *(float2*)(C + (size_t)r * ldc + col)       = v0;
            *(float2*)(C + (size_t)(r + 8) * ldc + col) = v1;
        }
    }
}

// ---------------- tensor-core 1x1 conv: C = relu6(W @ X + bias) -------------------
// A = W[r][k]; B = X[k][n] via [k][n] smem tile. Optional instance-norm of X.
// TRANSOUT=1 -> C[n][r] via smem-staged transpose. Double-buffered smem.
template<int SPLIT, int TRANSOUT>
__global__ __launch_bounds__(256, 1)
void conv_mma(const float* __restrict__ Wg, const float* __restrict__ Xg,
              const float* __restrict__ bias,
              const float* __restrict__ mean, const float* __restrict__ inv,
              float* __restrict__ Cg, int K, int ldc, size_t bC)
{
    constexpr int SROW = SPLIT ? 68 : 36;
    constexpr int ABUF = 128 * SROW;
    constexpr int XBUF = (SPLIT ? 2 : 1) * 32 * 132;
    extern __shared__ float smf[];
    float* SAbase = smf;                  // 2 x ABUF
    float* XSbase = smf + 2 * ABUF;       // 2 x XBUF
    float* stage  = smf;                  // epilogue overlay [128n][132]

    const int tid  = threadIdx.x;
    const int wid  = tid >> 5, lane = tid & 31;
    const int wm   = wid & 3,  wn2  = wid >> 2;
    const int lr   = lane >> 2, lc  = lane & 3;
    const int rbase = tid >> 3;
    const int c4    = (tid & 7) * 4;
    const int kk    = tid >> 5;
    const int n4    = (tid & 31) * 4;

    const int b  = blockIdx.z;
    const int n0 = blockIdx.x * 128;
    const int r0 = blockIdx.y * 128;
    const float* X = Xg + (size_t)b * K * NT;
    const float* mu = mean ? mean + b * K : nullptr;
    const float* iv = inv  ? inv  + b * K : nullptr;
    float* C = Cg + b * bC;

    float acc[2][8][4];
#pragma unroll
    for (int mi = 0; mi < 2; mi++)
#pragma unroll
        for (int nj = 0; nj < 8; nj++)
#pragma unroll
            for (int q = 0; q < 4; q++) acc[mi][nj][q] = 0.f;

    float4 pa[4], px[4];
    float pm[4], pv[4];
#pragma unroll
    for (int i = 0; i < 4; i++) {
        pa[i] = *(const float4*)(Wg + (size_t)(r0 + rbase + 32 * i) * K + c4);
        int k = kk + 8 * i;
        px[i] = *(const float4*)(X + (size_t)k * NT + n0 + n4);
        pm[i] = mu ? mu[k] : 0.f;
        pv[i] = iv ? iv[k] : 1.f;
    }

    const int NCH = K / 32;

    // store chunk 0 into buffer 0
    {
        float* SA  = SAbase;
        float* XS0 = XSbase;
        float* XS1 = XS0 + 32 * 132;
#pragma unroll
        for (int i = 0; i < 4; i++) {
            int r = rbase + 32 * i;
            if (SPLIT) {
                float4 hi, lo;
                hi.x = tf32rna(pa[i].x); lo.x = pa[i].x - hi.x;
                hi.y = tf32rna(pa[i].y); lo.y = pa[i].y - hi.y;
                hi.z = tf32rna(pa[i].z); lo.z = pa[i].z - hi.z;
                hi.w = tf32rna(pa[i].w); lo.w = pa[i].w - hi.w;
                *(float4*)(SA + r * SROW + c4)      = hi;
                *(float4*)(SA + r * SROW + 32 + c4) = lo;
            } else {
                float4 v = pa[i];
                v.x = tf32rna(v.x); v.y = tf32rna(v.y);
                v.z = tf32rna(v.z); v.w = tf32rna(v.w);
                *(float4*)(SA + r * SROW + c4) = v;
            }
        }
#pragma unroll
        for (int i = 0; i < 4; i++) {
            int k = kk + 8 * i;
            float4 v = px[i];
            v.x = (v.x - pm[i]) * pv[i]; v.y = (v.y - pm[i]) * pv[i];
            v.z = (v.z - pm[i]) * pv[i]; v.w = (v.w - pm[i]) * pv[i];
            if (SPLIT) {
                float4 hi, lo;
                hi.x = tf32rna(v.x); lo.x = v.x - hi.x;
                hi.y = tf32rna(v.y); lo.y = v.y - hi.y;
                hi.z = tf32rna(v.z); lo.z = v.z - hi.z;
                hi.w = tf32rna(v.w); lo.w = v.w - hi.w;
                *(float4*)(XS0 + k * 132 + n4) = hi;
                *(float4*)(XS1 + k * 132 + n4) = lo;
            } else {
                v.x = tf32rna(v.x); v.y = tf32rna(v.y);
                v.z = tf32rna(v.z); v.w = tf32rna(v.w);
                *(float4*)(XS0 + k * 132 + n4) = v;
            }
        }
    }
    __syncthreads();

    for (int c = 0; c < NCH; c++) {
        const int cur = c & 1;
        const bool more = (c + 1 < NCH);
        if (more) {
#pragma unroll
            for (int i = 0; i < 4; i++) {
                pa[i] = *(const float4*)(Wg + (size_t)(r0 + rbase + 32 * i) * K + (c + 1) * 32 + c4);
                int k = (c + 1) * 32 + kk + 8 * i;
                px[i] = *(const float4*)(X + (size_t)k * NT + n0 + n4);
                pm[i] = mu ? mu[k] : 0.f;
                pv[i] = iv ? iv[k] : 1.f;
            }
        }
        const uint32_t* UA  = (const uint32_t*)(SAbase + cur * ABUF);
        const uint32_t* UX0 = (const uint32_t*)(XSbase + cur * XBUF);
        const uint32_t* UX1 = UX0 + 32 * 132;
#pragma unroll
        for (int ks = 0; ks < 4; ks++) {
            const int k0 = ks * 8;
            uint32_t ah[2][4], bh[8][2];
#pragma unroll
            for (int mi = 0; mi < 2; mi++) {
                int base = (wm * 32 + mi * 16 + lr) * SROW + k0 + lc;
                ah[mi][0] = UA[base];            ah[mi][1] = UA[base + 8 * SROW];
                ah[mi][2] = UA[base + 4];        ah[mi][3] = UA[base + 8 * SROW + 4];
            }
#pragma unroll
            for (int nj = 0; nj < 8; nj++) {
                int col = wn2 * 64 + nj * 8 + lr;
                bh[nj][0] = UX0[(k0 + lc) * 132 + col];
                bh[nj][1] = UX0[(k0 + lc + 4) * 132 + col];
            }
#pragma unroll
            for (int mi = 0; mi < 2; mi++)
#pragma unroll
                for (int nj = 0; nj < 8; nj++)
                    mma8(acc[mi][nj], ah[mi], bh[nj]);
            if (SPLIT) {
                uint32_t al[2][4], bl[8][2];
#pragma unroll
                for (int mi = 0; mi < 2; mi++) {
                    int base = (wm * 32 + mi * 16 + lr) * SROW + 32 + k0 + lc;
                    al[mi][0] = UA[base];        al[mi][1] = UA[base + 8 * SROW];
                    al[mi][2] = UA[base + 4];    al[mi][3] = UA[base + 8 * SROW + 4];
                }
#pragma unroll
                for (int nj = 0; nj < 8; nj++) {
                    int col = wn2 * 64 + nj * 8 + lr;
                    bl[nj][0] = UX1[(k0 + lc) * 132 + col];
                    bl[nj][1] = UX1[(k0 + lc + 4) * 132 + col];
                }
#pragma unroll
                for (int mi = 0; mi < 2; mi++)
#pragma unroll
                    for (int nj = 0; nj < 8; nj++) {
                        mma8(acc[mi][nj], ah[mi], bl[nj]);
                        mma8(acc[mi][nj], al[mi], bh[nj]);
                    }
            }
        }
        if (more) {
            float* SA  = SAbase + (cur ^ 1) * ABUF;
            float* XS0 = XSbase + (cur ^ 1) * XBUF;
            float* XS1 = XS0 + 32 * 132;
#pragma unroll
            for (int i = 0; i < 4; i++) {
                int r = rbase + 32 * i;
                if (SPLIT) {
                    float4 hi, lo;
                    hi.x = tf32rna(pa[i].x); lo.x = pa[i].x - hi.x;
                    hi.y = tf32rna(pa[i].y); lo.y = pa[i].y - hi.y;
                    hi.z = tf32rna(pa[i].z); lo.z = pa[i].z - hi.z;
                    hi.w = tf32rna(pa[i].w); lo.w = pa[i].w - hi.w;
                    *(float4*)(SA + r * SROW + c4)      = hi;
                    *(float4*)(SA + r * SROW + 32 + c4) = lo;
                } else {
                    float4 v = pa[i];
                    v.x = tf32rna(v.x); v.y = tf32rna(v.y);
                    v.z = tf32rna(v.z); v.w = tf32rna(v.w);
                    *(float4*)(SA + r * SROW + c4) = v;
                }
            }
#pragma unroll
            for (int i = 0; i < 4; i++) {
                int k = kk + 8 * i;
                float4 v = px[i];
                v.x = (v.x - pm[i]) * pv[i]; v.y = (v.y - pm[i]) * pv[i];
                v.z = (v.z - pm[i]) * pv[i]; v.w = (v.w - pm[i]) * pv[i];
                if (SPLIT) {
                    float4 hi, lo;
                    hi.x = tf32rna(v.x); lo.x = v.x - hi.x;
                    hi.y = tf32rna(v.y); lo.y = v.y - hi.y;
                    hi.z = tf32rna(v.z); lo.z = v.z - hi.z;
                    hi.w = tf32rna(v.w); lo.w = v.w - hi.w;
                    *(float4*)(XS0 + k * 132 + n4) = hi;
                    *(float4*)(XS1 + k * 132 + n4) = lo;
                } else {
                    v.x = tf32rna(v.x); v.y = tf32rna(v.y);
                    v.z = tf32rna(v.z); v.w = tf32rna(v.w);
                    *(float4*)(XS0 + k * 132 + n4) = v;
                }
            }
        }
        __syncthreads();
    }

    if (!TRANSOUT) {
#pragma unroll
        for (int mi = 0; mi < 2; mi++) {
            int r = wm * 32 + mi * 16 + lr;
            float b0 = bias[r0 + r], b1 = bias[r0 + r + 8];
#pragma unroll
            for (int nj = 0; nj < 8; nj++) {
                int col = wn2 * 64 + nj * 8 + lc * 2;
                float2 v0 = make_float2(relu6f(acc[mi][nj][0] + b0),
                                        relu6f(acc[mi][nj][1] + b0));
                float2 v1 = make_float2(relu6f(acc[mi][nj][2] + b1),
                                        relu6f(acc[mi][nj][3] + b1));
                *(float2*)(C + (size_t)(r0 + r) * ldc + n0 + col)     = v0;
                *(float2*)(C + (size_t)(r0 + r + 8) * ldc + n0 + col) = v1;
            }
        }
    } else {
#pragma unroll
        for (int mi = 0; mi < 2; mi++) {
            int r = wm * 32 + mi * 16 + lr;
            float b0 = bias[r0 + r], b1 = bias[r0 + r + 8];
#pragma unroll
            for (int nj = 0; nj < 8; nj++) {
                int nl = wn2 * 64 + nj * 8 + lc * 2;
                stage[(size_t)nl * 132 + r]           = relu6f(acc[mi][nj][0] + b0);
                stage[(size_t)(nl + 1) * 132 + r]     = relu6f(acc[mi][nj][1] + b0);
                stage[(size_t)nl * 132 + r + 8]       = relu6f(acc[mi][nj][2] + b1);
                stage[(size_t)(nl + 1) * 132 + r + 8] = relu6f(acc[mi][nj][3] + b1);
            }
        }
        __syncthreads();
#pragma unroll
        for (int i = 0; i < 16; i++) {
            int e = tid + i * 256;
            int n = e >> 5, r4 = (e & 31) * 4;
            *(float4*)(C + (size_t)(n0 + n) * ldc + r0 + r4) = *(const float4*)(stage + n * 132 + r4);
        }
    }
}

// ---------------- row stats for softmax: off[row] = max + ln(sum exp) ------------
__global__ __launch_bounds__(256) void rowstat_kernel(const float* __restrict__ S,
                                                      float* __restrict__ off) {
    const float* p = S + (size_t)blockIdx.x * NT;
    int tid = threadIdx.x;
    float4 v[4];
    float mx = -1e30f;
#pragma unroll
    for (int i = 0; i < 4; i++) {
        v[i] = ((const float4*)p)[tid + i * 256];
        mx = fmaxf(mx, fmaxf(fmaxf(v[i].x, v[i].y), fmaxf(v[i].z, v[i].w)));
    }
    __shared__ float redm[8], reds[8];
#pragma unroll
    for (int o = 16; o; o >>= 1) mx = fmaxf(mx, __shfl_xor_sync(0xffffffffu, mx, o));
    if ((tid & 31) == 0) redm[tid >> 5] = mx;
    __syncthreads();
    mx = fmaxf(fmaxf(fmaxf(redm[0], redm[1]), fmaxf(redm[2], redm[3])),
               fmaxf(fmaxf(redm[4], redm[5]), fmaxf(redm[6], redm[7])));
    float s = 0.f;
#pragma unroll
    for (int i = 0; i < 4; i++) {
        s += __expf(v[i].x - mx) + __expf(v[i].y - mx)
           + __expf(v[i].z - mx) + __expf(v[i].w - mx);
    }
#pragma unroll
    for (int o = 16; o; o >>= 1) s += __shfl_xor_sync(0xffffffffu, s, o);
    if ((tid & 31) == 0) reds[tid >> 5] = s;
    __syncthreads();
    if (tid == 0) {
        s = reds[0] + reds[1] + reds[2] + reds[3] + reds[4] + reds[5] + reds[6] + reds[7];
        off[blockIdx.x] = mx + logf(s);
    }
}

// ---------------- launch ----------------
extern "C" void kernel_launch(void* const* d_in, const int* in_sizes, int n_in,
                              void* d_out, int out_size) {
    const float* Fc    = (const float*)d_in[0];
    const float* Fs    = (const float*)d_in[1];
    const float* f_w   = (const float*)d_in[2];
    const float* f_b   = (const float*)d_in[3];
    const float* g_w   = (const float*)d_in[4];
    const float* g_b   = (const float*)d_in[5];
    const float* h_w   = (const float*)d_in[6];
    const float* h_b   = (const float*)d_in[7];
    const float* out_w = (const float*)d_in[8];
    const float* out_b = (const float*)d_in[9];
    float* out = (float*)d_out;

    float *pfT, *pgT, *ph, *pfcs, *pS, *psoff, *pmean, *pinv;
    cudaGetSymbolAddress((void**)&pfT,   d_fT);
    cudaGetSymbolAddress((void**)&pgT,   d_gT);
    cudaGetSymbolAddress((void**)&ph,    d_h);
    cudaGetSymbolAddress((void**)&pfcs,  d_fcs);
    cudaGetSymbolAddress((void**)&pS,    d_S);
    cudaGetSymbolAddress((void**)&psoff, d_soff);
    cudaGetSymbolAddress((void**)&pmean, d_mean);
    cudaGetSymbolAddress((void**)&pinv,  d_inv);

    const int SM_G1 = 4 * 128 * 68 * 4;                   // 139264 (split gemm, 2-stage)
    const int SM_G0 = 4 * 128 * 36 * 4;                   // 73728
    const int SM_C1 = (2 * 128 * 68 + 4 * 32 * 132) * 4;  // 137216 (split conv, 2-stage)
    const int SM_C0 = (2 * 128 * 36 + 2 * 32 * 132) * 4;  // 70656
    cudaFuncSetAttribute(mma_gemm<1, 0, 0>, cudaFuncAttributeMaxDynamicSharedMemorySize, SM_G1);
    cudaFuncSetAttribute(mma_gemm<0, 0, 1>, cudaFuncAttributeMaxDynamicSharedMemorySize, SM_G0);
    cudaFuncSetAttribute(mma_gemm<0, 1, 0>, cudaFuncAttributeMaxDynamicSharedMemorySize, SM_G0);
    cudaFuncSetAttribute(conv_mma<1, 1>,    cudaFuncAttributeMaxDynamicSharedMemorySize, SM_C1);
    cudaFuncSetAttribute(conv_mma<0, 0>,    cudaFuncAttributeMaxDynamicSharedMemorySize, SM_C0);

    stats_kernel<<<dim3(BATCH * CIN, 2), 256>>>(Fc, Fs);

    // fT[n][d] = relu6(f_w @ mvn(Fc) + f_b)^T   (3xtf32)
    conv_mma<1, 1><<<dim3(NT / 128, CH / 128, BATCH), 256, SM_C1>>>(
        f_w, Fc, f_b, pmean, pinv, pfT, CIN, CH, (size_t)NT * CH);
    // gT[m][d] = relu6(g_w @ mvn(Fs) + g_b)^T   (3xtf32)
    conv_mma<1, 1><<<dim3(NT / 128, CH / 128, BATCH), 256, SM_C1>>>(
        g_w, Fs, g_b, pmean + BATCH * CIN, pinv + BATCH * CIN, pgT, CIN, CH, (size_t)NT * CH);
    // h[d][m] = relu6(h_w @ Fs + h_b)           (1xtf32)
    conv_mma<0, 0><<<dim3(NT / 128, CH / 128, BATCH), 256, SM_C0>>>(
        h_w, Fs, h_b, nullptr, nullptr, ph, CIN, NT, (size_t)CH * NT);

    // S[n][m] = fT . gT^T   (3xtf32)
    mma_gemm<1, 0, 0><<<dim3(NT / 128, NT / 128, BATCH), 256, SM_G1>>>(
        pfT, pgT, nullptr, nullptr, pS, CH, CH, CH, NT,
        (size_t)NT * CH, (size_t)NT * CH, (size_t)NT * NT);

    // per-row max + ln(sum exp)   (read-only pass)
    rowstat_kernel<<<BATCH * NT, 256>>>(pS, psoff);

    // fcs[n][d] = softmax(S) . h^T   (1xtf32, exp applied at A-tile store)
    mma_gemm<0, 0, 1><<<dim3(CH / 128, NT / 128, BATCH), 256, SM_G0>>>(
        pS, ph, nullptr, psoff, pfcs, NT, NT, NT, CH,
        (size_t)NT * NT, (size_t)CH * NT, (size_t)NT * CH);

    // out[r][n] = relu6(out_w @ fcs^T + out_b)  (1xtf32)
    mma_gemm<0, 1, 0><<<dim3(NT / 128, CIN / 128, BATCH), 256, SM_G0>>>(
        out_w, pfcs, out_b, nullptr, out, CH, CH, CH, NT,
        (size_t)0, (size_t)NT * CH, (size_t)CIN * NT);
}

// round 14
// speedup vs baseline: 1.3387x; 1.2885x over previous
#include <cuda_runtime.h>
#include <cuda_bf16.h>
#include <cstdint>
#include <cstddef>

#define NT    4096      // H*W tokens
#define CH    256       // hidden channels
#define CIN   512       // input channels
#define BATCH 4
#define SROW  36        // smem row stride (words), ≡4 mod 32 -> conflict-free fragments

// ---------------- scratch (device globals; no allocation in kernel_launch) --------
__device__ float d_fT [(size_t)BATCH * NT * CH];   // fT [b][n][d]
__device__ float d_gT [(size_t)BATCH * NT * CH];   // gT [b][m][d]
__device__ float d_h  [(size_t)BATCH * CH * NT];   // h  [b][d][m]
__device__ float d_fcs[(size_t)BATCH * NT * CH];   // Fcs[b][n][d]
__device__ float d_S  [(size_t)BATCH * NT * NT];   // scores [b][n][m]
__device__ float d_soff[(size_t)BATCH * NT];       // per-row max + ln(sum)
__device__ float d_mean[2 * BATCH * CIN];
__device__ float d_inv [2 * BATCH * CIN];

__device__ __forceinline__ float relu6f(float x) { return fminf(fmaxf(x, 0.0f), 6.0f); }
__device__ __forceinline__ float tf32rna(float x) {
    float r; asm("cvt.rna.tf32.f32 %0, %1;" : "=f"(r) : "f"(x)); return r;
}
// m16n8k8 tf32 MMA (baseline PTX, sm_80+)
__device__ __forceinline__ void mma8(float* d, const uint32_t* a, const uint32_t* b) {
    asm volatile("mma.sync.aligned.m16n8k8.row.col.f32.tf32.tf32.f32 "
                 "{%0,%1,%2,%3},{%4,%5,%6,%7},{%8,%9},{%0,%1,%2,%3};"
                 : "+f"(d[0]), "+f"(d[1]), "+f"(d[2]), "+f"(d[3])
                 : "r"(a[0]), "r"(a[1]), "r"(a[2]), "r"(a[3]), "r"(b[0]), "r"(b[1]));
}
// m16n8k16 bf16 MMA (baseline PTX, sm_80+) — 2x MAC rate of tf32 m16n8k8
__device__ __forceinline__ void mma16(float* d, const uint32_t* a, const uint32_t* b) {
    asm volatile("mma.sync.aligned.m16n8k16.row.col.f32.bf16.bf16.f32 "
                 "{%0,%1,%2,%3},{%4,%5,%6,%7},{%8,%9},{%0,%1,%2,%3};"
                 : "+f"(d[0]), "+f"(d[1]), "+f"(d[2]), "+f"(d[3])
                 : "r"(a[0]), "r"(a[1]), "r"(a[2]), "r"(a[3]), "r"(b[0]), "r"(b[1]));
}

// Store 4 consecutive k floats of one tile row into smem.
// MODE 0: tf32-rounded floats at word col c4 (32 words/row used).
// MODE 1: bf16 hi pairs at word col c4/2, lo pairs at +16 (k-pairs packed in words).
template<int MODE>
__device__ __forceinline__ void tile_store(float* S, int r, int c4, float4 v) {
    if (MODE == 0) {
        v.x = tf32rna(v.x); v.y = tf32rna(v.y);
        v.z = tf32rna(v.z); v.w = tf32rna(v.w);
        *(float4*)(S + r * SROW + c4) = v;
    } else {
        __nv_bfloat162 h0 = __floats2bfloat162_rn(v.x, v.y);
        __nv_bfloat162 h1 = __floats2bfloat162_rn(v.z, v.w);
        float2 f0 = __bfloat1622float2(h0);
        float2 f1 = __bfloat1622float2(h1);
        __nv_bfloat162 l0 = __floats2bfloat162_rn(v.x - f0.x, v.y - f0.y);
        __nv_bfloat162 l1 = __floats2bfloat162_rn(v.z - f1.x, v.w - f1.y);
        uint32_t* W = (uint32_t*)(S + r * SROW) + (c4 >> 1);
        uint2 hw = make_uint2(*(uint32_t*)&h0, *(uint32_t*)&h1);
        uint2 lw = make_uint2(*(uint32_t*)&l0, *(uint32_t*)&l1);
        *(uint2*)(W)      = hw;
        *(uint2*)(W + 16) = lw;
    }
}

// ---------------- per-(b,c) instance-norm stats, ddof=1 ----------------
__global__ __launch_bounds__(256) void stats_kernel(const float* __restrict__ Fc,
                                                    const float* __restrict__ Fs) {
    int inst  = blockIdx.x;
    int which = blockIdx.y;
    const float* src = (which ? Fs : Fc) + (size_t)inst * NT;
    int tid = threadIdx.x;
    float s = 0.f, ss = 0.f;
    for (int e = tid; e < NT / 4; e += 256) {
        float4 v = ((const float4*)src)[e];
        s  += v.x + v.y + v.z + v.w;
        ss += v.x * v.x + v.y * v.y + v.z * v.z + v.w * v.w;
    }
    for (int o = 16; o; o >>= 1) {
        s  += __shfl_xor_sync(0xffffffffu, s, o);
        ss += __shfl_xor_sync(0xffffffffu, ss, o);
    }
    __shared__ float sb[8], ssb[8];
    if ((tid & 31) == 0) { sb[tid >> 5] = s; ssb[tid >> 5] = ss; }
    __syncthreads();
    if (tid == 0) {
        s = 0.f; ss = 0.f;
        for (int w = 0; w < 8; w++) { s += sb[w]; ss += ssb[w]; }
        float mean = s / (float)NT;
        float var  = (ss - s * mean) / (float)(NT - 1);
        d_mean[which * BATCH * CIN + inst] = mean;
        d_inv [which * BATCH * CIN + inst] = rsqrtf(var + 1e-5f);
    }
}

// ---------------- MMA GEMM: C[M,N] = A[M,K] * B[N,K]^T ---------------------------
// CTA tile 128x128, K-chunk 32, 8 warps (32x64 warp tile), double-buffered smem.
// MODE 0: single tf32. MODE 1: 2-way split bf16 (hi/lo, 3 products).
// EXPA (MODE0 only): A transformed p = exp(a - aoff[row]) at smem-store time.
template<int MODE, int ACT, int EXPA>
__global__ __launch_bounds__(256, 1)
void mma_gemm(const float* __restrict__ Ag, const float* __restrict__ Bg,
              const float* __restrict__ bias, const float* __restrict__ aoffg,
              float* __restrict__ Cg,
              int K, int lda, int ldb, int ldc,
              size_t bA, size_t bB, size_t bC)
{
    constexpr int TBUF = 128 * SROW;
    extern __shared__ float smf[];
    float* SAbase = smf;                 // 2 x TBUF
    float* SBbase = smf + 2 * TBUF;      // 2 x TBUF

    const int tid  = threadIdx.x;
    const int wid  = tid >> 5, lane = tid & 31;
    const int wm   = wid & 3,  wn   = wid >> 2;
    const int lr   = lane >> 2, lc  = lane & 3;
    const int rbase = tid >> 3;
    const int c4    = (tid & 7) * 4;

    const float* A = Ag + blockIdx.z * bA + (size_t)(blockIdx.y * 128) * lda;
    const float* B = Bg + blockIdx.z * bB + (size_t)(blockIdx.x * 128) * ldb;
    float*       C = Cg + blockIdx.z * bC + (size_t)(blockIdx.y * 128) * ldc + blockIdx.x * 128;

    float acc[2][8][4];
#pragma unroll
    for (int mi = 0; mi < 2; mi++)
#pragma unroll
        for (int nj = 0; nj < 8; nj++)
#pragma unroll
            for (int q = 0; q < 4; q++) acc[mi][nj][q] = 0.f;

    float po[4];
    if (EXPA) {
        const float* Ao = aoffg + blockIdx.z * NT + blockIdx.y * 128;
#pragma unroll
        for (int i = 0; i < 4; i++) po[i] = Ao[rbase + 32 * i];
    }

    float4 pa[4], pb[4];
#pragma unroll
    for (int i = 0; i < 4; i++) {
        pa[i] = *(const float4*)(A + (size_t)(rbase + 32 * i) * lda + c4);
        pb[i] = *(const float4*)(B + (size_t)(rbase + 32 * i) * ldb + c4);
    }

    const int NCH = K / 32;

    // store chunk 0 into buffer 0
    {
#pragma unroll
        for (int i = 0; i < 4; i++) {
            int r = rbase + 32 * i;
            float4 va = pa[i];
            if (EXPA) {
                va.x = __expf(va.x - po[i]); va.y = __expf(va.y - po[i]);
                va.z = __expf(va.z - po[i]); va.w = __expf(va.w - po[i]);
            }
            tile_store<MODE>(SAbase, r, c4, va);
            tile_store<MODE>(SBbase, r, c4, pb[i]);
        }
    }
    __syncthreads();

    for (int c = 0; c < NCH; c++) {
        const int cur = c & 1;
        const bool more = (c + 1 < NCH);
        if (more) {
#pragma unroll
            for (int i = 0; i < 4; i++) {
                pa[i] = *(const float4*)(A + (size_t)(rbase + 32 * i) * lda + (c + 1) * 32 + c4);
                pb[i] = *(const float4*)(B + (size_t)(rbase + 32 * i) * ldb + (c + 1) * 32 + c4);
            }
        }
        const uint32_t* UA = (const uint32_t*)(SAbase + cur * TBUF);
        const uint32_t* UB = (const uint32_t*)(SBbase + cur * TBUF);
        if (MODE == 0) {
#pragma unroll
            for (int ks = 0; ks < 4; ks++) {
                const int k0 = ks * 8;
                uint32_t ah[2][4], bh[8][2];
#pragma unroll
                for (int mi = 0; mi < 2; mi++) {
                    int base = (wm * 32 + mi * 16 + lr) * SROW + k0 + lc;
                    ah[mi][0] = UA[base];            ah[mi][1] = UA[base + 8 * SROW];
                    ah[mi][2] = UA[base + 4];        ah[mi][3] = UA[base + 8 * SROW + 4];
                }
#pragma unroll
                for (int nj = 0; nj < 8; nj++) {
                    int base = (wn * 64 + nj * 8 + lr) * SROW + k0 + lc;
                    bh[nj][0] = UB[base];            bh[nj][1] = UB[base + 4];
                }
#pragma unroll
                for (int mi = 0; mi < 2; mi++)
#pragma unroll
                    for (int nj = 0; nj < 8; nj++)
                        mma8(acc[mi][nj], ah[mi], bh[nj]);
            }
        } else {
#pragma unroll
            for (int s = 0; s < 2; s++) {
                const int k0 = s * 8;    // word offset within hi region
                uint32_t ah[2][4], al[2][4], bh[8][2], bl[8][2];
#pragma unroll
                for (int mi = 0; mi < 2; mi++) {
                    int base = (wm * 32 + mi * 16 + lr) * SROW + k0 + lc;
                    ah[mi][0] = UA[base];            ah[mi][1] = UA[base + 8 * SROW];
                    ah[mi][2] = UA[base + 4];        ah[mi][3] = UA[base + 8 * SROW + 4];
                    al[mi][0] = UA[base + 16];       al[mi][1] = UA[base + 8 * SROW + 16];
                    al[mi][2] = UA[base + 20];       al[mi][3] = UA[base + 8 * SROW + 20];
                }
#pragma unroll
                for (int nj = 0; nj < 8; nj++) {
                    int base = (wn * 64 + nj * 8 + lr) * SROW + k0 + lc;
                    bh[nj][0] = UB[base];            bh[nj][1] = UB[base + 4];
                    bl[nj][0] = UB[base + 16];       bl[nj][1] = UB[base + 20];
                }
#pragma unroll
                for (int mi = 0; mi < 2; mi++)
#pragma unroll
                    for (int nj = 0; nj < 8; nj++) {
                        mma16(acc[mi][nj], ah[mi], bh[nj]);
                        mma16(acc[mi][nj], ah[mi], bl[nj]);
                        mma16(acc[mi][nj], al[mi], bh[nj]);
                    }
            }
        }
        if (more) {
            float* SA = SAbase + (cur ^ 1) * TBUF;
            float* SB = SBbase + (cur ^ 1) * TBUF;
#pragma unroll
            for (int i = 0; i < 4; i++) {
                int r = rbase + 32 * i;
                float4 va = pa[i];
                if (EXPA) {
                    va.x = __expf(va.x - po[i]); va.y = __expf(va.y - po[i]);
                    va.z = __expf(va.z - po[i]); va.w = __expf(va.w - po[i]);
                }
                tile_store<MODE>(SA, r, c4, va);
                tile_store<MODE>(SB, r, c4, pb[i]);
            }
        }
        __syncthreads();
    }

#pragma unroll
    for (int mi = 0; mi < 2; mi++) {
        int r = wm * 32 + mi * 16 + lr;
        float b0 = 0.f, b1 = 0.f;
        if (ACT) {
            b0 = bias[blockIdx.y * 128 + r];
            b1 = bias[blockIdx.y * 128 + r + 8];
        }
#pragma unroll
        for (int nj = 0; nj < 8; nj++) {
            int col = wn * 64 + nj * 8 + lc * 2;
            float2 v0 = make_float2(acc[mi][nj][0], acc[mi][nj][1]);
            float2 v1 = make_float2(acc[mi][nj][2], acc[mi][nj][3]);
            if (ACT) {
                v0.x = relu6f(v0.x + b0); v0.y = relu6f(v0.y + b0);
                v1.x = relu6f(v1.x + b1); v1.y = relu6f(v1.y + b1);
            }
            *(float2*)(C + (size_t)r * ldc + col)       = v0;
            *(float2*)(C + (size_t)(r + 8) * ldc + col) = v1;
        }
    }
}

// ---------------- tensor-core 1x1 conv: C = relu6(W @ X + bias) -------------------
// A = W[r][k]; B = X[k][n] via [k][n] smem tile (MODE1: k-pairs packed per word).
// Optional instance-norm of X. TRANSOUT=1 -> C[n][r] via smem-staged transpose.
template<int MODE, int TRANSOUT>
__global__ __launch_bounds__(256, 1)
void conv_mma(const float* __restrict__ Wg, const float* __restrict__ Xg,
              const float* __restrict__ bias,
              const float* __restrict__ mean, const float* __restrict__ inv,
              float* __restrict__ Cg, int K, int ldc, size_t bC)
{
    constexpr int ABUF = 128 * SROW;    // 4608 words
    constexpr int XBUF = 32 * 132;      // 4224 words (MODE1: hi 16x132 + lo 16x132)
    extern __shared__ float smf[];
    float* SAbase = smf;                  // 2 x ABUF
    float* XSbase = smf + 2 * ABUF;       // 2 x XBUF
    float* stage  = smf;                  // epilogue overlay [128n][132]

    const int tid  = threadIdx.x;
    const int wid  = tid >> 5, lane = tid & 31;
    const int wm   = wid & 3,  wn2  = wid >> 2;
    const int lr   = lane >> 2, lc  = lane & 3;
    const int rbase = tid >> 3;
    const int c4    = (tid & 7) * 4;
    const int kk    = tid >> 5;          // 0..7
    const int n4    = (tid & 31) * 4;

    const int b  = blockIdx.z;
    const int n0 = blockIdx.x * 128;
    const int r0 = blockIdx.y * 128;
    const float* X = Xg + (size_t)b * K * NT;
    const float* mu = mean ? mean + b * K : nullptr;
    const float* iv = inv  ? inv  + b * K : nullptr;
    float* C = Cg + b * bC;

    float acc[2][8][4];
#pragma unroll
    for (int mi = 0; mi < 2; mi++)
#pragma unroll
        for (int nj = 0; nj < 8; nj++)
#pragma unroll
            for (int q = 0; q < 4; q++) acc[mi][nj][q] = 0.f;

    float4 pa[4], px[4];
    float pm[4], pv[4];

    // prefetch W + X for chunk c into registers
    auto prefetch = [&](int c) {
#pragma unroll
        for (int i = 0; i < 4; i++)
            pa[i] = *(const float4*)(Wg + (size_t)(r0 + rbase + 32 * i) * K + c * 32 + c4);
        if (MODE == 0) {
#pragma unroll
            for (int i = 0; i < 4; i++) {
                int k = c * 32 + kk + 8 * i;
                px[i] = *(const float4*)(X + (size_t)k * NT + n0 + n4);
                pm[i] = mu ? mu[k] : 0.f;
                pv[i] = iv ? iv[k] : 1.f;
            }
        } else {
#pragma unroll
            for (int i = 0; i < 2; i++) {
                int kg = c * 32 + 2 * (kk + 8 * i);
                px[2 * i]     = *(const float4*)(X + (size_t)kg * NT + n0 + n4);
                px[2 * i + 1] = *(const float4*)(X + (size_t)(kg + 1) * NT + n0 + n4);
                pm[2 * i]     = mu ? mu[kg] : 0.f;
                pv[2 * i]     = iv ? iv[kg] : 1.f;
                pm[2 * i + 1] = mu ? mu[kg + 1] : 0.f;
                pv[2 * i + 1] = iv ? iv[kg + 1] : 1.f;
            }
        }
    };

    // store prefetched chunk into smem buffer
    auto store_buf = [&](int buf) {
        float* SA  = SAbase + buf * ABUF;
        float* XS0 = XSbase + buf * XBUF;
#pragma unroll
        for (int i = 0; i < 4; i++)
            tile_store<MODE>(SA, rbase + 32 * i, c4, pa[i]);
        if (MODE == 0) {
#pragma unroll
            for (int i = 0; i < 4; i++) {
                int k = kk + 8 * i;
                float4 v = px[i];
                v.x = (v.x - pm[i]) * pv[i]; v.y = (v.y - pm[i]) * pv[i];
                v.z = (v.z - pm[i]) * pv[i]; v.w = (v.w - pm[i]) * pv[i];
                v.x = tf32rna(v.x); v.y = tf32rna(v.y);
                v.z = tf32rna(v.z); v.w = tf32rna(v.w);
                *(float4*)(XS0 + k * 132 + n4) = v;
            }
        } else {
            float* XS1 = XS0 + 16 * 132;
#pragma unroll
            for (int i = 0; i < 2; i++) {
                int kp = kk + 8 * i;       // local k-pair row 0..15
                float4 xe = px[2 * i], xo = px[2 * i + 1];
                xe.x = (xe.x - pm[2*i]) * pv[2*i]; xe.y = (xe.y - pm[2*i]) * pv[2*i];
                xe.z = (xe.z - pm[2*i]) * pv[2*i]; xe.w = (xe.w - pm[2*i]) * pv[2*i];
                xo.x = (xo.x - pm[2*i+1]) * pv[2*i+1]; xo.y = (xo.y - pm[2*i+1]) * pv[2*i+1];
                xo.z = (xo.z - pm[2*i+1]) * pv[2*i+1]; xo.w = (xo.w - pm[2*i+1]) * pv[2*i+1];
                float e[4] = {xe.x, xe.y, xe.z, xe.w};
                float o[4] = {xo.x, xo.y, xo.z, xo.w};
                uint32_t hw[4], lw[4];
#pragma unroll
                for (int j = 0; j < 4; j++) {
                    __nv_bfloat162 h = __floats2bfloat162_rn(e[j], o[j]);
                    float2 hf = __bfloat1622float2(h);
                    __nv_bfloat162 l = __floats2bfloat162_rn(e[j] - hf.x, o[j] - hf.y);
                    hw[j] = *(uint32_t*)&h;
                    lw[j] = *(uint32_t*)&l;
                }
                *(uint4*)((uint32_t*)XS0 + kp * 132 + n4) = make_uint4(hw[0], hw[1], hw[2], hw[3]);
                *(uint4*)((uint32_t*)XS1 + kp * 132 + n4) = make_uint4(lw[0], lw[1], lw[2], lw[3]);
            }
        }
    };

    const int NCH = K / 32;
    prefetch(0);
    store_buf(0);
    __syncthreads();

    for (int c = 0; c < NCH; c++) {
        const int cur = c & 1;
        const bool more = (c + 1 < NCH);
        if (more) prefetch(c + 1);

        const uint32_t* UA  = (const uint32_t*)(SAbase + cur * ABUF);
        const uint32_t* UX0 = (const uint32_t*)(XSbase + cur * XBUF);
        if (MODE == 0) {
#pragma unroll
            for (int ks = 0; ks < 4; ks++) {
                const int k0 = ks * 8;
                uint32_t ah[2][4], bh[8][2];
#pragma unroll
                for (int mi = 0; mi < 2; mi++) {
                    int base = (wm * 32 + mi * 16 + lr) * SROW + k0 + lc;
                    ah[mi][0] = UA[base];            ah[mi][1] = UA[base + 8 * SROW];
                    ah[mi][2] = UA[base + 4];        ah[mi][3] = UA[base + 8 * SROW + 4];
                }
#pragma unroll
                for (int nj = 0; nj < 8; nj++) {
                    int col = wn2 * 64 + nj * 8 + lr;
                    bh[nj][0] = UX0[(k0 + lc) * 132 + col];
                    bh[nj][1] = UX0[(k0 + lc + 4) * 132 + col];
                }
#pragma unroll
                for (int mi = 0; mi < 2; mi++)
#pragma unroll
                    for (int nj = 0; nj < 8; nj++)
                        mma8(acc[mi][nj], ah[mi], bh[nj]);
            }
        } else {
            const uint32_t* UX1 = UX0 + 16 * 132;
#pragma unroll
            for (int s = 0; s < 2; s++) {
                const int k0 = s * 8;
                uint32_t ah[2][4], al[2][4], bh[8][2], bl[8][2];
#pragma unroll
                for (int mi = 0; mi < 2; mi++) {
                    int base = (wm * 32 + mi * 16 + lr) * SROW + k0 + lc;
                    ah[mi][0] = UA[base];            ah[mi][1] = UA[base + 8 * SROW];
                    ah[mi][2] = UA[base + 4];        ah[mi][3] = UA[base + 8 * SROW + 4];
                    al[mi][0] = UA[base + 16];       al[mi][1] = UA[base + 8 * SROW + 16];
                    al[mi][2] = UA[base + 20];       al[mi][3] = UA[base + 8 * SROW + 20];
                }
#pragma unroll
                for (int nj = 0; nj < 8; nj++) {
                    int col = wn2 * 64 + nj * 8 + lr;
                    bh[nj][0] = UX0[(k0 + lc) * 132 + col];
                    bh[nj][1] = UX0[(k0 + lc + 4) * 132 + col];
                    bl[nj][0] = UX1[(k0 + lc) * 132 + col];
                    bl[nj][1] = UX1[(k0 + lc + 4) * 132 + col];
                }
#pragma unroll
                for (int mi = 0; mi < 2; mi++)
#pragma unroll
                    for (int nj = 0; nj < 8; nj++) {
                        mma16(acc[mi][nj], ah[mi], bh[nj]);
                        mma16(acc[mi][nj], ah[mi], bl[nj]);
                        mma16(acc[mi][nj], al[mi], bh[nj]);
                    }
            }
        }
        if (more) store_buf(cur ^ 1);
        __syncthreads();
    }

    if (!TRANSOUT) {
#pragma unroll
        for (int mi = 0; mi < 2; mi++) {
            int r = wm * 32 + mi * 16 + lr;
            float b0 = bias[r0 + r], b1 = bias[r0 + r + 8];
#pragma unroll
            for (int nj = 0; nj < 8; nj++) {
                int col = wn2 * 64 + nj * 8 + lc * 2;
                float2 v0 = make_float2(relu6f(acc[mi][nj][0] + b0),
                                        relu6f(acc[mi][nj][1] + b0));
                float2 v1 = make_float2(relu6f(acc[mi][nj][2] + b1),
                                        relu6f(acc[mi][nj][3] + b1));
                *(float2*)(C + (size_t)(r0 + r) * ldc + n0 + col)     = v0;
                *(float2*)(C + (size_t)(r0 + r + 8) * ldc + n0 + col) = v1;
            }
        }
    } else {
#pragma unroll
        for (int mi = 0; mi < 2; mi++) {
            int r = wm * 32 + mi * 16 + lr;
            float b0 = bias[r0 + r], b1 = bias[r0 + r + 8];
#pragma unroll
            for (int nj = 0; nj < 8; nj++) {
                int nl = wn2 * 64 + nj * 8 + lc * 2;
                stage[(size_t)nl * 132 + r]           = relu6f(acc[mi][nj][0] + b0);
                stage[(size_t)(nl + 1) * 132 + r]     = relu6f(acc[mi][nj][1] + b0);
                stage[(size_t)nl * 132 + r + 8]       = relu6f(acc[mi][nj][2] + b1);
                stage[(size_t)(nl + 1) * 132 + r + 8] = relu6f(acc[mi][nj][3] + b1);
            }
        }
        __syncthreads();
#pragma unroll
        for (int i = 0; i < 16; i++) {
            int e = tid + i * 256;
            int n = e >> 5, r4 = (e & 31) * 4;
            *(float4*)(C + (size_t)(n0 + n) * ldc + r0 + r4) = *(const float4*)(stage + n * 132 + r4);
        }
    }
}

// ---------------- row stats for softmax: off[row] = max + ln(sum exp) ------------
__global__ __launch_bounds__(256) void rowstat_kernel(const float* __restrict__ S,
                                                      float* __restrict__ off) {
    const float* p = S + (size_t)blockIdx.x * NT;
    int tid = threadIdx.x;
    float4 v[4];
    float mx = -1e30f;
#pragma unroll
    for (int i = 0; i < 4; i++) {
        v[i] = ((const float4*)p)[tid + i * 256];
        mx = fmaxf(mx, fmaxf(fmaxf(v[i].x, v[i].y), fmaxf(v[i].z, v[i].w)));
    }
    __shared__ float redm[8], reds[8];
#pragma unroll
    for (int o = 16; o; o >>= 1) mx = fmaxf(mx, __shfl_xor_sync(0xffffffffu, mx, o));
    if ((tid & 31) == 0) redm[tid >> 5] = mx;
    __syncthreads();
    mx = fmaxf(fmaxf(fmaxf(redm[0], redm[1]), fmaxf(redm[2], redm[3])),
               fmaxf(fmaxf(redm[4], redm[5]), fmaxf(redm[6], redm[7])));
    float s = 0.f;
#pragma unroll
    for (int i = 0; i < 4; i++) {
        s += __expf(v[i].x - mx) + __expf(v[i].y - mx)
           + __expf(v[i].z - mx) + __expf(v[i].w - mx);
    }
#pragma unroll
    for (int o = 16; o; o >>= 1) s += __shfl_xor_sync(0xffffffffu, s, o);
    if ((tid & 31) == 0) reds[tid >> 5] = s;
    __syncthreads();
    if (tid == 0) {
        s = reds[0] + reds[1] + reds[2] + reds[3] + reds[4] + reds[5] + reds[6] + reds[7];
        off[blockIdx.x] = mx + logf(s);
    }
}

// ---------------- launch ----------------
extern "C" void kernel_launch(void* const* d_in, const int* in_sizes, int n_in,
                              void* d_out, int out_size) {
    const float* Fc    = (const float*)d_in[0];
    const float* Fs    = (const float*)d_in[1];
    const float* f_w   = (const float*)d_in[2];
    const float* f_b   = (const float*)d_in[3];
    const float* g_w   = (const float*)d_in[4];
    const float* g_b   = (const float*)d_in[5];
    const float* h_w   = (const float*)d_in[6];
    const float* h_b   = (const float*)d_in[7];
    const float* out_w = (const float*)d_in[8];
    const float* out_b = (const float*)d_in[9];
    float* out = (float*)d_out;

    float *pfT, *pgT, *ph, *pfcs, *pS, *psoff, *pmean, *pinv;
    cudaGetSymbolAddress((void**)&pfT,   d_fT);
    cudaGetSymbolAddress((void**)&pgT,   d_gT);
    cudaGetSymbolAddress((void**)&ph,    d_h);
    cudaGetSymbolAddress((void**)&pfcs,  d_fcs);
    cudaGetSymbolAddress((void**)&pS,    d_S);
    cudaGetSymbolAddress((void**)&psoff, d_soff);
    cudaGetSymbolAddress((void**)&pmean, d_mean);
    cudaGetSymbolAddress((void**)&pinv,  d_inv);

    const int SM_G = 4 * 128 * SROW * 4;                    // 73728 (2-stage A+B)
    const int SM_C = (2 * 128 * SROW + 2 * 32 * 132) * 4;   // 70656
    cudaFuncSetAttribute(mma_gemm<1, 0, 0>, cudaFuncAttributeMaxDynamicSharedMemorySize, SM_G);
    cudaFuncSetAttribute(mma_gemm<0, 0, 1>, cudaFuncAttributeMaxDynamicSharedMemorySize, SM_G);
    cudaFuncSetAttribute(mma_gemm<0, 1, 0>, cudaFuncAttributeMaxDynamicSharedMemorySize, SM_G);
    cudaFuncSetAttribute(conv_mma<1, 1>,    cudaFuncAttributeMaxDynamicSharedMemorySize, SM_C);
    cudaFuncSetAttribute(conv_mma<0, 0>,    cudaFuncAttributeMaxDynamicSharedMemorySize, SM_C);

    stats_kernel<<<dim3(BATCH * CIN, 2), 256>>>(Fc, Fs);

    // fT[n][d] = relu6(f_w @ mvn(Fc) + f_b)^T   (bf16 split)
    conv_mma<1, 1><<<dim3(NT / 128, CH / 128, BATCH), 256, SM_C>>>(
        f_w, Fc, f_b, pmean, pinv, pfT, CIN, CH, (size_t)NT * CH);
    // gT[m][d] = relu6(g_w @ mvn(Fs) + g_b)^T   (bf16 split)
    conv_mma<1, 1><<<dim3(NT / 128, CH / 128, BATCH), 256, SM_C>>>(
        g_w, Fs, g_b, pmean + BATCH * CIN, pinv + BATCH * CIN, pgT, CIN, CH, (size_t)NT * CH);
    // h[d][m] = relu6(h_w @ Fs + h_b)           (1xtf32)
    conv_mma<0, 0><<<dim3(NT / 128, CH / 128, BATCH), 256, SM_C>>>(
        h_w, Fs, h_b, nullptr, nullptr, ph, CIN, NT, (size_t)CH * NT);

    // S[n][m] = fT . gT^T   (bf16 split)
    mma_gemm<1, 0, 0><<<dim3(NT / 128, NT / 128, BATCH), 256, SM_G>>>(
        pfT, pgT, nullptr, nullptr, pS, CH, CH, CH, NT,
        (size_t)NT * CH, (size_t)NT * CH, (size_t)NT * NT);

    // per-row max + ln(sum exp)   (read-only pass)
    rowstat_kernel<<<BATCH * NT, 256>>>(pS, psoff);

    // fcs[n][d] = softmax(S) . h^T   (1xtf32, exp applied at A-tile store)
    mma_gemm<0, 0, 1><<<dim3(CH / 128, NT / 128, BATCH), 256, SM_G>>>(
        pS, ph, nullptr, psoff, pfcs, NT, NT, NT, CH,
        (size_t)NT * NT, (size_t)CH * NT, (size_t)NT * CH);

    // out[r][n] = relu6(out_w @ fcs^T + out_b)  (1xtf32)
    mma_gemm<0, 1, 0><<<dim3(NT / 128, CIN / 128, BATCH), 256, SM_G>>>(
        out_w, pfcs, out_b, nullptr, out, CH, CH, CH, NT,
        (size_t)0, (size_t)NT * CH, (size_t)CIN * NT);
}